// round 15
// baseline (speedup 1.0000x reference)
#include <cuda_runtime.h>

#define FULLMASK 0xffffffffu
typedef unsigned long long ull;

// ---------------- packed f32x2 helpers ----------------
__device__ __forceinline__ ull pk(float lo, float hi) {
    ull r; asm("mov.b64 %0, {%1, %2};" : "=l"(r) : "f"(lo), "f"(hi)); return r;
}
__device__ __forceinline__ void upk(ull v, float &lo, float &hi) {
    asm("mov.b64 {%0, %1}, %2;" : "=f"(lo), "=f"(hi) : "l"(v));
}
__device__ __forceinline__ ull fma2(ull a, ull b, ull c) {
    ull d; asm("fma.rn.f32x2 %0, %1, %2, %3;" : "=l"(d) : "l"(a), "l"(b), "l"(c)); return d;
}
__device__ __forceinline__ ull mul2(ull a, ull b) {
    ull d; asm("mul.rn.f32x2 %0, %1, %2;" : "=l"(d) : "l"(a), "l"(b)); return d;
}
__device__ __forceinline__ ull shfl2(ull v, int lm) {
    float lo, hi; upk(v, lo, hi);
    lo = __shfl_xor_sync(FULLMASK, lo, lm);
    hi = __shfl_xor_sync(FULLMASK, hi, lm);
    return pk(lo, hi);
}
__device__ __forceinline__ ull shfl2i(ull v, int src) {
    float lo, hi; upk(v, lo, hi);
    lo = __shfl_sync(FULLMASK, lo, src);
    hi = __shfl_sync(FULLMASK, hi, src);
    return pk(lo, hi);
}

// ---------------- precomputed params ----------------
__device__ float  g_ry[32];      // [gate 0..15][cy,sy]
__device__ float2 g_phase[512];  // [l*256 + slot], slot = (k&31)*8 + (k>>5)
__device__ float  g_W1f[128];    // BN folded into W1
__device__ float  g_b1f[8];

__global__ void prep_kernel(const float* __restrict__ qw,
                            const float* __restrict__ g,
                            const float* __restrict__ b,
                            const float* __restrict__ rm,
                            const float* __restrict__ rv,
                            const float* __restrict__ W1,
                            const float* __restrict__ b1) {
    __shared__ float s_phi[16];
    __shared__ float s_scale[16], s_shift[16];
    int t = threadIdx.x;
    if (t < 16) {
        float sy, cy;
        sincosf(0.5f * qw[t * 2 + 0], &sy, &cy);       // RY half-angle
        g_ry[t * 2 + 0] = cy; g_ry[t * 2 + 1] = sy;
        s_phi[t] = 0.5f * qw[t * 2 + 1];               // RZ half-angle
        float sc = g[t] * rsqrtf(rv[t] + 1e-5f);
        s_scale[t] = sc;
        s_shift[t] = b[t] - rm[t] * sc;
    }
    __syncthreads();
    {
        // Plain phase tables: theta_l(k) = sum_w (bit(7-w) of k ? +phi : -phi).
        int k = t;
        float th0 = 0.f, th1 = 0.f;
        #pragma unroll
        for (int w = 0; w < 8; ++w) {
            int bit = 7 - w;
            th0 += ((k >> bit) & 1) ? s_phi[w]     : -s_phi[w];
            th1 += ((k >> bit) & 1) ? s_phi[8 + w] : -s_phi[8 + w];
        }
        float c0, s0, c1, s1;
        sincosf(th0, &s0, &c0);
        sincosf(th1, &s1, &c1);
        // slot for conflict-free per-r reads: slot = (k&31)*8 + (k>>5)
        int slot = (k & 31) * 8 + (k >> 5);
        g_phase[slot]       = make_float2(c0, s0);
        g_phase[256 + slot] = make_float2(c1, s1);
    }
    if (t < 128) g_W1f[t] = s_scale[t >> 3] * W1[t];
    if (t < 8) {
        float acc = b1[t];
        #pragma unroll
        for (int kk = 0; kk < 16; ++kk) acc += s_shift[kk] * W1[kk * 8 + t];
        g_b1f[t] = acc;
    }
}

// FOUR samples per warp: sample = lane bits 4..3 (grp), amplitude k (8 bits):
//   bits 7..5 = La = lane&7, bits 4..0 = reg r (32 complex regs per thread).
// CNOT perm new[k] = old[k^(k>>1)]: srcLane = gray3(La) (in 8-lane group),
//   src reg = gray5(rd) ^ (parity(publisher La)<<4)  (publish-side 1-bit select).
__global__ __launch_bounds__(256, 1) void qml_kernel(const float* __restrict__ x,
                                                     const float* __restrict__ W2,
                                                     const float* __restrict__ b2,
                                                     float* __restrict__ out) {
    __shared__ float2 sPh[512];
    __shared__ float  sRy[32];
    __shared__ float  sW1f[128];
    __shared__ float  sb1f[8];
    __shared__ float  sW2[16];
    __shared__ float  sb2[2];

    int tid = threadIdx.x;
    {
        sPh[tid]       = g_phase[tid];
        sPh[tid + 256] = g_phase[tid + 256];
        if (tid < 32)        sRy[tid] = g_ry[tid];
        else if (tid < 160)  sW1f[tid - 32] = g_W1f[tid - 32];
        else if (tid < 168)  sb1f[tid - 160] = g_b1f[tid - 160];
        else if (tid < 184)  sW2[tid - 168] = W2[tid - 168];
        else if (tid < 186)  sb2[tid - 184] = b2[tid - 184];
    }
    __syncthreads();

    const int warpid = tid >> 5;
    const int lane = tid & 31;
    const int La = lane & 7;
    const int grp = lane >> 3;
    const int sample = blockIdx.x * 32 + warpid * 4 + grp;

    // Permutation constants
    const int psrc = (lane & 24) | (La ^ (La >> 1));  // gray3 within 8-lane group
    const int myp  = __popc(La) & 1;

    // ---- load 32 amps (k = La*32 + idx), un-normalized ----
    const float4* xp = reinterpret_cast<const float4*>(x + (size_t)sample * 256 + La * 32);
    float a[32];
    #pragma unroll
    for (int i = 0; i < 8; ++i) {
        float4 v = xp[i];
        a[i*4+0] = v.x; a[i*4+1] = v.y; a[i*4+2] = v.z; a[i*4+3] = v.w;
    }
    float nrm2 = 0.f;
    #pragma unroll
    for (int i = 0; i < 32; ++i) nrm2 += a[i] * a[i];

    // ---- Layer 1 RYs (real). Pack (a[j], a[j+16]) -> z[j]; pack dim = amp bit 4 (wire 3).
    ull z[16];
    #pragma unroll
    for (int j = 0; j < 16; ++j) z[j] = pk(a[j], a[j + 16]);

    // wires 0..2: lane-bit gates, masks 4,2,1 (within 8-lane group)
    #pragma unroll
    for (int w = 0; w < 3; ++w) {
        const int lmask = 4 >> w;
        const float cy = sRy[w * 2], sy = sRy[w * 2 + 1];
        const float se = (lane & lmask) ? sy : -sy;
        const ull cy2 = pk(cy, cy), se2 = pk(se, se);
        #pragma unroll
        for (int j = 0; j < 16; ++j)
            z[j] = fma2(cy2, z[j], mul2(se2, shfl2(z[j], lmask)));
    }
    // wire 3 (pack dim): in-reg rotate
    {
        const float cy = sRy[6], sy = sRy[7];
        #pragma unroll
        for (int j = 0; j < 16; ++j) {
            float e0, e1; upk(z[j], e0, e1);
            z[j] = pk(cy * e0 - sy * e1, sy * e0 + cy * e1);
        }
    }
    // complex-pair macro: lo' = c*lo - s*hi ; hi' = s*lo_old + c*hi
    #define RPAIR(arr, lo_, hi_) { ull tt = arr[lo_]; \
        arr[lo_] = fma2(cy2, arr[lo_], mul2(sn2, arr[hi_])); \
        arr[hi_] = fma2(cy2, arr[hi_], mul2(sp2, tt)); }
    // wire 4 (z bit3): pairs (j, j^8)
    {
        const float cy = sRy[8], sy = sRy[9];
        const ull cy2 = pk(cy, cy), sp2 = pk(sy, sy), sn2 = pk(-sy, -sy);
        #pragma unroll
        for (int j = 0; j < 8; ++j) RPAIR(z, j, j + 8)
    }
    // wire 5 (z bit2): (j, j^4)
    {
        const float cy = sRy[10], sy = sRy[11];
        const ull cy2 = pk(cy, cy), sp2 = pk(sy, sy), sn2 = pk(-sy, -sy);
        #pragma unroll
        for (int j = 0; j < 16; ++j) if (!(j & 4)) RPAIR(z, j, j + 4)
    }
    // wire 6 (z bit1): (j, j^2)
    {
        const float cy = sRy[12], sy = sRy[13];
        const ull cy2 = pk(cy, cy), sp2 = pk(sy, sy), sn2 = pk(-sy, -sy);
        #pragma unroll
        for (int j = 0; j < 16; ++j) if (!(j & 2)) RPAIR(z, j, j + 2)
    }
    // wire 7 (z bit0): (j, j^1)
    {
        const float cy = sRy[14], sy = sRy[15];
        const ull cy2 = pk(cy, cy), sp2 = pk(sy, sy), sn2 = pk(-sy, -sy);
        #pragma unroll
        for (int j = 0; j < 16; ++j) if (!(j & 1)) RPAIR(z, j, j + 1)
    }

    // ---- Layer-1 RZ: complexify, s[r] = a_post[r] * phase0(k) ----
    ull s[32];
    #pragma unroll
    for (int j = 0; j < 16; ++j) {
        float e0, e1; upk(z[j], e0, e1);
        float2 ph0 = sPh[j * 8 + La];
        float2 ph1 = sPh[(j + 16) * 8 + La];
        s[j]      = pk(e0 * ph0.x, e0 * ph0.y);
        s[j + 16] = pk(e1 * ph1.x, e1 * ph1.y);
    }

    // Permutation: dest r reads src reg gray5(r) (^16 if publisher parity set).
    // Branch-free SEL keeps lanes converged for the shfl.
    #define DO_PERM() { \
        ull n0,n1,n2,n3,n4,n5,n6,n7,n8,n9,n10,n11,n12,n13,n14,n15, \
            n16,n17,n18,n19,n20,n21,n22,n23,n24,n25,n26,n27,n28,n29,n30,n31; \
        n0  = shfl2i(myp ? s[16] : s[0],  psrc); \
        n1  = shfl2i(myp ? s[17] : s[1],  psrc); \
        n2  = shfl2i(myp ? s[19] : s[3],  psrc); \
        n3  = shfl2i(myp ? s[18] : s[2],  psrc); \
        n4  = shfl2i(myp ? s[22] : s[6],  psrc); \
        n5  = shfl2i(myp ? s[23] : s[7],  psrc); \
        n6  = shfl2i(myp ? s[21] : s[5],  psrc); \
        n7  = shfl2i(myp ? s[20] : s[4],  psrc); \
        n8  = shfl2i(myp ? s[28] : s[12], psrc); \
        n9  = shfl2i(myp ? s[29] : s[13], psrc); \
        n10 = shfl2i(myp ? s[31] : s[15], psrc); \
        n11 = shfl2i(myp ? s[30] : s[14], psrc); \
        n12 = shfl2i(myp ? s[26] : s[10], psrc); \
        n13 = shfl2i(myp ? s[27] : s[11], psrc); \
        n14 = shfl2i(myp ? s[25] : s[9],  psrc); \
        n15 = shfl2i(myp ? s[24] : s[8],  psrc); \
        n16 = shfl2i(myp ? s[8]  : s[24], psrc); \
        n17 = shfl2i(myp ? s[9]  : s[25], psrc); \
        n18 = shfl2i(myp ? s[11] : s[27], psrc); \
        n19 = shfl2i(myp ? s[10] : s[26], psrc); \
        n20 = shfl2i(myp ? s[14] : s[30], psrc); \
        n21 = shfl2i(myp ? s[15] : s[31], psrc); \
        n22 = shfl2i(myp ? s[13] : s[29], psrc); \
        n23 = shfl2i(myp ? s[12] : s[28], psrc); \
        n24 = shfl2i(myp ? s[4]  : s[20], psrc); \
        n25 = shfl2i(myp ? s[5]  : s[21], psrc); \
        n26 = shfl2i(myp ? s[7]  : s[23], psrc); \
        n27 = shfl2i(myp ? s[6]  : s[22], psrc); \
        n28 = shfl2i(myp ? s[2]  : s[18], psrc); \
        n29 = shfl2i(myp ? s[3]  : s[19], psrc); \
        n30 = shfl2i(myp ? s[1]  : s[17], psrc); \
        n31 = shfl2i(myp ? s[0]  : s[16], psrc); \
        s[0]=n0; s[1]=n1; s[2]=n2; s[3]=n3; s[4]=n4; s[5]=n5; s[6]=n6; s[7]=n7; \
        s[8]=n8; s[9]=n9; s[10]=n10; s[11]=n11; s[12]=n12; s[13]=n13; s[14]=n14; s[15]=n15; \
        s[16]=n16; s[17]=n17; s[18]=n18; s[19]=n19; s[20]=n20; s[21]=n21; s[22]=n22; s[23]=n23; \
        s[24]=n24; s[25]=n25; s[26]=n26; s[27]=n27; s[28]=n28; s[29]=n29; s[30]=n30; s[31]=n31; \
    }

    // ---- CNOT chain #1 ----
    DO_PERM()

    // ---- Layer 2 RYs (complex) ----
    // wires 0..2: lane-bit gates, masks 4,2,1
    #pragma unroll
    for (int w = 0; w < 3; ++w) {
        const int lmask = 4 >> w;
        const float cy = sRy[16 + w * 2], sy = sRy[16 + w * 2 + 1];
        const float se = (lane & lmask) ? sy : -sy;
        const ull cy2 = pk(cy, cy), se2 = pk(se, se);
        #pragma unroll
        for (int r = 0; r < 32; ++r)
            s[r] = fma2(cy2, s[r], mul2(se2, shfl2(s[r], lmask)));
    }
    // wire 3 (bit4): (r, r^16)
    {
        const float cy = sRy[22], sy = sRy[23];
        const ull cy2 = pk(cy, cy), sp2 = pk(sy, sy), sn2 = pk(-sy, -sy);
        #pragma unroll
        for (int r = 0; r < 16; ++r) RPAIR(s, r, r + 16)
    }
    // wire 4 (bit3): (r, r^8)
    {
        const float cy = sRy[24], sy = sRy[25];
        const ull cy2 = pk(cy, cy), sp2 = pk(sy, sy), sn2 = pk(-sy, -sy);
        #pragma unroll
        for (int r = 0; r < 32; ++r) if (!(r & 8)) RPAIR(s, r, r + 8)
    }
    // wire 5 (bit2): (r, r^4)
    {
        const float cy = sRy[26], sy = sRy[27];
        const ull cy2 = pk(cy, cy), sp2 = pk(sy, sy), sn2 = pk(-sy, -sy);
        #pragma unroll
        for (int r = 0; r < 32; ++r) if (!(r & 4)) RPAIR(s, r, r + 4)
    }
    // wire 6 (bit1): (r, r^2)
    {
        const float cy = sRy[28], sy = sRy[29];
        const ull cy2 = pk(cy, cy), sp2 = pk(sy, sy), sn2 = pk(-sy, -sy);
        #pragma unroll
        for (int r = 0; r < 32; ++r) if (!(r & 2)) RPAIR(s, r, r + 2)
    }
    // wire 7 (bit0): (r, r^1)
    {
        const float cy = sRy[30], sy = sRy[31];
        const ull cy2 = pk(cy, cy), sp2 = pk(sy, sy), sn2 = pk(-sy, -sy);
        #pragma unroll
        for (int r = 0; r < 32; ++r) if (!(r & 1)) RPAIR(s, r, r + 1)
    }
    // ---- Layer-2 RZ ----
    #pragma unroll
    for (int r = 0; r < 32; ++r) {
        float2 ph = sPh[256 + r * 8 + La];
        float re, im; upk(s[r], re, im);
        s[r] = pk(ph.x * re - ph.y * im, ph.x * im + ph.y * re);
    }

    // ---- CNOT chain #2 ----
    DO_PERM()

    // ---- Measurements ----
    float p[32], sump = 0.f;
    #pragma unroll
    for (int r = 0; r < 32; ++r) {
        float lo, hi; upk(mul2(s[r], s[r]), lo, hi);
        p[r] = lo + hi;
        sump += p[r];
    }

    float q[17];
    // Z wires 0..2: sign from lane bit (4 >> w)
    #pragma unroll
    for (int w = 0; w < 3; ++w)
        q[w] = (lane & (4 >> w)) ? -sump : sump;
    // Z wires 3..7: sign from reg bit 4,3,2,1,0
    {
        float s3 = 0.f, s4 = 0.f, s5 = 0.f, s6 = 0.f, s7 = 0.f;
        #pragma unroll
        for (int r = 0; r < 32; ++r) {
            s3 += (r & 16) ? -p[r] : p[r];
            s4 += (r & 8)  ? -p[r] : p[r];
            s5 += (r & 4)  ? -p[r] : p[r];
            s6 += (r & 2)  ? -p[r] : p[r];
            s7 += (r & 1)  ? -p[r] : p[r];
        }
        q[3] = s3; q[4] = s4; q[5] = s5; q[6] = s6; q[7] = s7;
    }

    // X wires 0..2: lane masks 4,2,1; sum over all amps counts each pair twice
    #pragma unroll
    for (int w = 0; w < 3; ++w) {
        const int lmask = 4 >> w;
        ull acc = pk(0.f, 0.f);
        #pragma unroll
        for (int r = 0; r < 32; ++r)
            acc = fma2(s[r], shfl2(s[r], lmask), acc);
        float lo, hi; upk(acc, lo, hi);
        q[8 + w] = lo + hi;
    }
    // X wires 3..7: in-reg pairs, factor 2
    {
        ull acc = pk(0.f, 0.f);
        #pragma unroll
        for (int r = 0; r < 16; ++r) acc = fma2(s[r], s[r + 16], acc);
        float lo, hi; upk(acc, lo, hi);
        q[11] = 2.f * (lo + hi);
    }
    {
        ull acc = pk(0.f, 0.f);
        #pragma unroll
        for (int r = 0; r < 32; ++r) if (!(r & 8)) acc = fma2(s[r], s[r + 8], acc);
        float lo, hi; upk(acc, lo, hi);
        q[12] = 2.f * (lo + hi);
    }
    {
        ull acc = pk(0.f, 0.f);
        #pragma unroll
        for (int r = 0; r < 32; ++r) if (!(r & 4)) acc = fma2(s[r], s[r + 4], acc);
        float lo, hi; upk(acc, lo, hi);
        q[13] = 2.f * (lo + hi);
    }
    {
        ull acc = pk(0.f, 0.f);
        #pragma unroll
        for (int r = 0; r < 32; ++r) if (!(r & 2)) acc = fma2(s[r], s[r + 2], acc);
        float lo, hi; upk(acc, lo, hi);
        q[14] = 2.f * (lo + hi);
    }
    {
        ull acc = pk(0.f, 0.f);
        #pragma unroll
        for (int r = 0; r < 32; ++r) if (!(r & 1)) acc = fma2(s[r], s[r + 1], acc);
        float lo, hi; upk(acc, lo, hi);
        q[15] = 2.f * (lo + hi);
    }
    q[16] = nrm2;

    // ---- Full butterfly reduction within 8-lane group ----
    #pragma unroll
    for (int f = 0; f < 17; ++f) {
        q[f] += __shfl_xor_sync(FULLMASK, q[f], 4);
        q[f] += __shfl_xor_sync(FULLMASK, q[f], 2);
        q[f] += __shfl_xor_sync(FULLMASK, q[f], 1);
    }

    // ---- BN-folded MLP, register-local per lane (j = La) ----
    const float inv = 1.0f / q[16];
    const int j = La;
    float acc = sb1f[j];
    #pragma unroll
    for (int f = 0; f < 16; ++f)
        acc = fmaf(q[f] * inv, sW1f[f * 8 + j], acc);
    float h = fmaxf(acc, 0.f);
    float o0 = h * sW2[j * 2 + 0];
    float o1 = h * sW2[j * 2 + 1];
    #pragma unroll
    for (int off = 4; off > 0; off >>= 1) {
        o0 += __shfl_xor_sync(FULLMASK, o0, off);
        o1 += __shfl_xor_sync(FULLMASK, o1, off);
    }
    if (La == 0) {
        float2* op = reinterpret_cast<float2*>(out + (size_t)sample * 2);
        *op = make_float2(o0 + sb2[0], o1 + sb2[1]);
    }
    #undef RPAIR
    #undef DO_PERM
}

extern "C" void kernel_launch(void* const* d_in, const int* in_sizes, int n_in,
                              void* d_out, int out_size) {
    const float* x  = (const float*)d_in[0];
    const float* qw = (const float*)d_in[1];
    const float* g  = (const float*)d_in[2];
    const float* b  = (const float*)d_in[3];
    const float* rm = (const float*)d_in[4];
    const float* rv = (const float*)d_in[5];
    const float* W1 = (const float*)d_in[6];
    const float* b1 = (const float*)d_in[7];
    const float* W2 = (const float*)d_in[8];
    const float* b2 = (const float*)d_in[9];
    float* out = (float*)d_out;

    prep_kernel<<<1, 256>>>(qw, g, b, rm, rv, W1, b1);
    qml_kernel<<<2048, 256>>>(x, W2, b2, out);
}